// round 3
// baseline (speedup 1.0000x reference)
#include <cuda_runtime.h>
#include <cstdint>

// ============================================================================
// GVP fused kernel — round 2: conflict-free smem GEMM
//
// Per CTA: 64 nodes, 256 threads (8 warps).
// Stage-2 mapping: warp w owns nodes 8w..8w+7 (broadcast A reads),
// lane l owns output columns {2l+64q, 2l+64q+1 : q=0..3} (conflict-free
// LDS.64 B reads). A tile staged in smem pre-duplicated as (a,a) f32x2 pairs.
// Inner kk loop register double-buffered.
// ============================================================================

typedef unsigned long long ull;

#define TPB 256
#define NODES_PER_CTA 64

// smem layout (floats)
#define OFF_S    0        // S_s: 64*256 = 16384  (aliases Vtmp 64*96, dead after stage1)
#define OFF_VH   16384    // V_h: 6144
#define OFF_SH   22528    // s_h: 2048
#define OFF_WHT  24576    // 1024
#define OFF_WMUT 25600    // 1024
#define OFF_WG   26624    // W_g packed: 4096 ull = 8192 floats
#define OFF_A2   34816    // A2: 16k x 64n duplicated pairs = 1024 ull = 2048 floats
#define OFF_B    36864    // B_s: 16*256 = 4096
#define SMEM_FLOATS 40960
#define SMEM_BYTES (SMEM_FLOATS * 4)

__device__ float g_Wt[288 * 256];   // W_m_w transposed: [k][o]

__global__ void prep_transpose(const float* __restrict__ Wm) {
    int i = blockIdx.x * blockDim.x + threadIdx.x;
    if (i < 288 * 256) {
        int k = i >> 8, o = i & 255;
        g_Wt[i] = Wm[o * 288 + k];
    }
}

__device__ __forceinline__ ull pack2(float x) {
    ull d; asm("mov.b64 %0, {%1, %1};" : "=l"(d) : "f"(x)); return d;
}
__device__ __forceinline__ ull pack2(float x, float y) {
    ull d; asm("mov.b64 %0, {%1, %2};" : "=l"(d) : "f"(x), "f"(y)); return d;
}
__device__ __forceinline__ void fma2(ull& c, ull a, ull b) {
    asm("fma.rn.f32x2 %0, %1, %2, %3;" : "=l"(c) : "l"(a), "l"(b), "l"(c));
}
__device__ __forceinline__ float2 unpack2(ull v) {
    float2 r; asm("mov.b64 {%0, %1}, %2;" : "=f"(r.x), "=f"(r.y) : "l"(v)); return r;
}
__device__ __forceinline__ float sigmoidf_fast(float x) {
    return 1.0f / (1.0f + __expf(-x));
}

union F4U { float4 f; ull u[2]; };

__global__ void __launch_bounds__(TPB, 1) gvp_kernel(
    const float* __restrict__ s_g, const float* __restrict__ V_g,
    const float* __restrict__ Wh,  const float* __restrict__ Wmu,
    const float* __restrict__ Wmb, const float* __restrict__ Wg,
    const float* __restrict__ Wgb, float* __restrict__ out, int N)
{
    extern __shared__ float sm_[];
    float* S_s  = sm_ + OFF_S;
    float* Vtmp = sm_ + OFF_S;      // alias, dead after stage1
    float* Vh   = sm_ + OFF_VH;
    float* sh   = sm_ + OFF_SH;
    float* WhT  = sm_ + OFF_WHT;
    float* WmuT = sm_ + OFF_WMUT;
    ull*   WgP  = reinterpret_cast<ull*>(sm_ + OFF_WG);
    ull*   A2u  = reinterpret_cast<ull*>(sm_ + OFF_A2);
    float* B_s  = sm_ + OFF_B;
    ull*   B2u  = reinterpret_cast<ull*>(sm_ + OFF_B);

    const int t = threadIdx.x;
    const int node0 = blockIdx.x * NODES_PER_CTA;

    // ---------------- stage 0: stage weights + V tile ----------------
    {
        const float4* vg = reinterpret_cast<const float4*>(V_g + (size_t)node0 * 96);
        float4* vt = reinterpret_cast<float4*>(Vtmp);
        #pragma unroll
        for (int i = t; i < 1536; i += TPB) vt[i] = vg[i];

        #pragma unroll
        for (int i = t; i < 1024; i += TPB) {
            int r = i >> 5, c = i & 31;
            WhT[c * 32 + r]  = Wh[i];   // Wh[h][v] -> WhT[v][h]
            WmuT[c * 32 + r] = Wmu[i];  // Wmu[m][h] -> WmuT[h][m]
        }
        // W_g [32][256] -> packed layout [kp2][m][2] of ull k-pairs
        const ull* wg2 = reinterpret_cast<const ull*>(Wg);
        #pragma unroll
        for (int d = t; d < 4096; d += TPB) {
            int j = d & 1, m = (d >> 1) & 31, kp2 = d >> 6;
            WgP[(kp2 * 32 + m) * 2 + j] = wg2[(size_t)m * 128 + kp2 * 2 + j];
        }
    }
    __syncthreads();

    // ---------------- stage 1: V_h, s_h ----------------
    #pragma unroll
    for (int p = t; p < 2048; p += TPB) {
        int n = p >> 5, h = p & 31;
        float ax = 0.f, ay = 0.f, az = 0.f;
        const float* vrow = Vtmp + n * 96;
        #pragma unroll
        for (int v = 0; v < 32; v++) {
            float w = WhT[v * 32 + h];
            ax = fmaf(w, vrow[v * 3 + 0], ax);
            ay = fmaf(w, vrow[v * 3 + 1], ay);
            az = fmaf(w, vrow[v * 3 + 2], az);
        }
        Vh[n * 96 + h * 3 + 0] = ax;
        Vh[n * 96 + h * 3 + 1] = ay;
        Vh[n * 96 + h * 3 + 2] = az;
        sh[n * 32 + h] = fmaxf(sqrtf(ax * ax + ay * ay + az * az), 1e-4f);
    }
    __syncthreads();

    // ---------------- stage 2: main GEMM [64,288]x[288,256] ----------------
    const int w = t >> 5;   // warp: nodes 8w..8w+7
    const int l = t & 31;   // lane: cols 2l+64q

    ull acc[8][4];
    #pragma unroll
    for (int i = 0; i < 8; i++)
        #pragma unroll
        for (int q = 0; q < 4; q++) acc[i][q] = 0ull;

    // staging thread mapping
    const int an = t >> 2;          // node 0..63
    const int ak = (t & 3) << 2;    // k sub 0,4,8,12
    const int bk = t >> 6;          // 0..3
    const int bo = (t & 63) << 2;   // col

    float4 apre, bpre[4];
    apre = *reinterpret_cast<const float4*>(s_g + (size_t)(node0 + an) * 256 + ak);
    #pragma unroll
    for (int r = 0; r < 4; r++)
        bpre[r] = *reinterpret_cast<const float4*>(g_Wt + (bk + r * 4) * 256 + bo);

    #define LOAD_AB(kk, areg, breg)                                         \
        do {                                                                \
            _Pragma("unroll")                                               \
            for (int i_ = 0; i_ < 8; i_++)                                  \
                areg[i_] = A2u[(kk) * 64 + (w << 3) + i_];                  \
            _Pragma("unroll")                                               \
            for (int q_ = 0; q_ < 4; q_++)                                  \
                breg[q_] = B2u[(kk) * 128 + l + (q_ << 5)];                 \
        } while (0)

    #define FMA_STEP(areg, breg)                                            \
        do {                                                                \
            _Pragma("unroll")                                               \
            for (int i_ = 0; i_ < 8; i_++)                                  \
                _Pragma("unroll")                                           \
                for (int q_ = 0; q_ < 4; q_++)                              \
                    fma2(acc[i_][q_], areg[i_], breg[q_]);                  \
        } while (0)

    for (int c = 0; c < 18; c++) {
        __syncthreads();
        A2u[(ak + 0) * 64 + an] = pack2(apre.x);
        A2u[(ak + 1) * 64 + an] = pack2(apre.y);
        A2u[(ak + 2) * 64 + an] = pack2(apre.z);
        A2u[(ak + 3) * 64 + an] = pack2(apre.w);
        #pragma unroll
        for (int r = 0; r < 4; r++)
            *reinterpret_cast<float4*>(B_s + (bk + r * 4) * 256 + bo) = bpre[r];
        __syncthreads();

        if (c < 17) {   // register-prefetch next chunk
            int k0 = (c + 1) * 16;
            if (k0 < 256)
                apre = *reinterpret_cast<const float4*>(s_g + (size_t)(node0 + an) * 256 + k0 + ak);
            else
                apre = *reinterpret_cast<const float4*>(sh + an * 32 + (k0 - 256) + ak);
            #pragma unroll
            for (int r = 0; r < 4; r++)
                bpre[r] = *reinterpret_cast<const float4*>(g_Wt + (size_t)(k0 + bk + r * 4) * 256 + bo);
        }

        // register double-buffered kk loop
        ull aA[8], bA[4], aB[8], bB[4];
        LOAD_AB(0, aA, bA);
        #pragma unroll
        for (int kk = 0; kk < 16; kk += 2) {
            LOAD_AB(kk + 1, aB, bB);
            FMA_STEP(aA, bA);
            if (kk + 2 < 16) LOAD_AB(kk + 2, aA, bA);
            FMA_STEP(aB, bB);
        }
    }

    // ---------------- stage 3: bias + relu out + sigmoid to smem ----------------
    ull biasp[4];
    #pragma unroll
    for (int q = 0; q < 4; q++)
        biasp[q] = *reinterpret_cast<const ull*>(Wmb + 2 * l + 64 * q);

    #pragma unroll
    for (int i = 0; i < 8; i++) {
        int ln = (w << 3) + i;
        size_t gn = (size_t)(node0 + ln);
        #pragma unroll
        for (int q = 0; q < 4; q++) {
            float2 v = unpack2(acc[i][q]);
            float2 b = unpack2(biasp[q]);
            float m0 = v.x + b.x;
            float m1 = v.y + b.y;
            *reinterpret_cast<ull*>(out + gn * 256 + 2 * l + 64 * q) =
                pack2(fmaxf(m0, 0.f), fmaxf(m1, 0.f));
            *reinterpret_cast<ull*>(S_s + ln * 256 + 2 * l + 64 * q) =
                pack2(sigmoidf_fast(m0), sigmoidf_fast(m1));
        }
    }
    __syncthreads();

    // ---------------- stage 4: gate GEMM + V_mu + V_dash ----------------
    const int m  = t & 31;
    const int nb = t >> 5;   // nodes nb, nb+8, ..., nb+56

    ull ag[8];
    #pragma unroll
    for (int j = 0; j < 8; j++) ag[j] = 0ull;

    const float* WgF = sm_ + OFF_WG;
    for (int kp2 = 0; kp2 < 64; kp2++) {
        F4U wv;
        wv.f = *reinterpret_cast<const float4*>(WgF + (kp2 * 32 + m) * 4);
        #pragma unroll
        for (int j = 0; j < 8; j++) {
            F4U sv;
            sv.f = *reinterpret_cast<const float4*>(S_s + (nb + j * 8) * 256 + 4 * kp2);
            fma2(ag[j], sv.u[0], wv.u[0]);
            fma2(ag[j], sv.u[1], wv.u[1]);
        }
    }
    float gb = Wgb[m];
    float gate[8];
    #pragma unroll
    for (int j = 0; j < 8; j++) {
        float2 v = unpack2(ag[j]);
        gate[j] = sigmoidf_fast(v.x + v.y + gb);
    }

    #pragma unroll
    for (int j = 0; j < 8; j++) {
        int n = nb + j * 8;
        float ax = 0.f, ay = 0.f, az = 0.f;
        const float* vr = Vh + n * 96;
        #pragma unroll
        for (int h = 0; h < 32; h++) {
            float wmu = WmuT[h * 32 + m];
            ax = fmaf(wmu, vr[h * 3 + 0], ax);
            ay = fmaf(wmu, vr[h * 3 + 1], ay);
            az = fmaf(wmu, vr[h * 3 + 2], az);
        }
        float g = gate[j];
        size_t base = (size_t)N * 256 + ((size_t)(node0 + n) * 32 + m) * 3;
        out[base + 0] = g * ax;
        out[base + 1] = g * ay;
        out[base + 2] = g * az;
    }
}

extern "C" void kernel_launch(void* const* d_in, const int* in_sizes, int n_in,
                              void* d_out, int out_size) {
    const float* s   = (const float*)d_in[0];
    const float* V   = (const float*)d_in[1];
    const float* Wh  = (const float*)d_in[2];
    const float* Wmu = (const float*)d_in[3];
    const float* Wm  = (const float*)d_in[4];
    const float* Wmb = (const float*)d_in[5];
    const float* Wg  = (const float*)d_in[6];
    const float* Wgb = (const float*)d_in[7];
    float* out = (float*)d_out;

    const int N = in_sizes[0] / 256;

    cudaFuncSetAttribute(gvp_kernel, cudaFuncAttributeMaxDynamicSharedMemorySize, SMEM_BYTES);

    prep_transpose<<<(288 * 256 + 255) / 256, 256>>>(Wm);
    gvp_kernel<<<N / NODES_PER_CTA, TPB, SMEM_BYTES>>>(s, V, Wh, Wmu, Wmb, Wg, Wgb, out, N);
}

// round 4
// speedup vs baseline: 1.0029x; 1.0029x over previous
#include <cuda_runtime.h>
#include <cstdint>

// ============================================================================
// GVP fused kernel — round 2: conflict-free smem GEMM
//
// Per CTA: 64 nodes, 256 threads (8 warps).
// Stage-2 mapping: warp w owns nodes 8w..8w+7 (broadcast A reads),
// lane l owns output columns {2l+64q, 2l+64q+1 : q=0..3} (conflict-free
// LDS.64 B reads). A tile staged in smem pre-duplicated as (a,a) f32x2 pairs.
// Inner kk loop register double-buffered.
// ============================================================================

typedef unsigned long long ull;

#define TPB 256
#define NODES_PER_CTA 64

// smem layout (floats)
#define OFF_S    0        // S_s: 64*256 = 16384  (aliases Vtmp 64*96, dead after stage1)
#define OFF_VH   16384    // V_h: 6144
#define OFF_SH   22528    // s_h: 2048
#define OFF_WHT  24576    // 1024
#define OFF_WMUT 25600    // 1024
#define OFF_WG   26624    // W_g packed: 4096 ull = 8192 floats
#define OFF_A2   34816    // A2: 16k x 64n duplicated pairs = 1024 ull = 2048 floats
#define OFF_B    36864    // B_s: 16*256 = 4096
#define SMEM_FLOATS 40960
#define SMEM_BYTES (SMEM_FLOATS * 4)

__device__ float g_Wt[288 * 256];   // W_m_w transposed: [k][o]

__global__ void prep_transpose(const float* __restrict__ Wm) {
    int i = blockIdx.x * blockDim.x + threadIdx.x;
    if (i < 288 * 256) {
        int k = i >> 8, o = i & 255;
        g_Wt[i] = Wm[o * 288 + k];
    }
}

__device__ __forceinline__ ull pack2(float x) {
    ull d; asm("mov.b64 %0, {%1, %1};" : "=l"(d) : "f"(x)); return d;
}
__device__ __forceinline__ ull pack2(float x, float y) {
    ull d; asm("mov.b64 %0, {%1, %2};" : "=l"(d) : "f"(x), "f"(y)); return d;
}
__device__ __forceinline__ void fma2(ull& c, ull a, ull b) {
    asm("fma.rn.f32x2 %0, %1, %2, %3;" : "=l"(c) : "l"(a), "l"(b), "l"(c));
}
__device__ __forceinline__ float2 unpack2(ull v) {
    float2 r; asm("mov.b64 {%0, %1}, %2;" : "=f"(r.x), "=f"(r.y) : "l"(v)); return r;
}
__device__ __forceinline__ float sigmoidf_fast(float x) {
    return 1.0f / (1.0f + __expf(-x));
}

union F4U { float4 f; ull u[2]; };

__global__ void __launch_bounds__(TPB, 1) gvp_kernel(
    const float* __restrict__ s_g, const float* __restrict__ V_g,
    const float* __restrict__ Wh,  const float* __restrict__ Wmu,
    const float* __restrict__ Wmb, const float* __restrict__ Wg,
    const float* __restrict__ Wgb, float* __restrict__ out, int N)
{
    extern __shared__ float sm_[];
    float* S_s  = sm_ + OFF_S;
    float* Vtmp = sm_ + OFF_S;      // alias, dead after stage1
    float* Vh   = sm_ + OFF_VH;
    float* sh   = sm_ + OFF_SH;
    float* WhT  = sm_ + OFF_WHT;
    float* WmuT = sm_ + OFF_WMUT;
    ull*   WgP  = reinterpret_cast<ull*>(sm_ + OFF_WG);
    ull*   A2u  = reinterpret_cast<ull*>(sm_ + OFF_A2);
    float* B_s  = sm_ + OFF_B;
    ull*   B2u  = reinterpret_cast<ull*>(sm_ + OFF_B);

    const int t = threadIdx.x;
    const int node0 = blockIdx.x * NODES_PER_CTA;

    // ---------------- stage 0: stage weights + V tile ----------------
    {
        const float4* vg = reinterpret_cast<const float4*>(V_g + (size_t)node0 * 96);
        float4* vt = reinterpret_cast<float4*>(Vtmp);
        #pragma unroll
        for (int i = t; i < 1536; i += TPB) vt[i] = vg[i];

        #pragma unroll
        for (int i = t; i < 1024; i += TPB) {
            int r = i >> 5, c = i & 31;
            WhT[c * 32 + r]  = Wh[i];   // Wh[h][v] -> WhT[v][h]
            WmuT[c * 32 + r] = Wmu[i];  // Wmu[m][h] -> WmuT[h][m]
        }
        // W_g [32][256] -> packed layout [kp2][m][2] of ull k-pairs
        const ull* wg2 = reinterpret_cast<const ull*>(Wg);
        #pragma unroll
        for (int d = t; d < 4096; d += TPB) {
            int j = d & 1, m = (d >> 1) & 31, kp2 = d >> 6;
            WgP[(kp2 * 32 + m) * 2 + j] = wg2[(size_t)m * 128 + kp2 * 2 + j];
        }
    }
    __syncthreads();

    // ---------------- stage 1: V_h, s_h ----------------
    #pragma unroll
    for (int p = t; p < 2048; p += TPB) {
        int n = p >> 5, h = p & 31;
        float ax = 0.f, ay = 0.f, az = 0.f;
        const float* vrow = Vtmp + n * 96;
        #pragma unroll
        for (int v = 0; v < 32; v++) {
            float w = WhT[v * 32 + h];
            ax = fmaf(w, vrow[v * 3 + 0], ax);
            ay = fmaf(w, vrow[v * 3 + 1], ay);
            az = fmaf(w, vrow[v * 3 + 2], az);
        }
        Vh[n * 96 + h * 3 + 0] = ax;
        Vh[n * 96 + h * 3 + 1] = ay;
        Vh[n * 96 + h * 3 + 2] = az;
        sh[n * 32 + h] = fmaxf(sqrtf(ax * ax + ay * ay + az * az), 1e-4f);
    }
    __syncthreads();

    // ---------------- stage 2: main GEMM [64,288]x[288,256] ----------------
    const int w = t >> 5;   // warp: nodes 8w..8w+7
    const int l = t & 31;   // lane: cols 2l+64q

    ull acc[8][4];
    #pragma unroll
    for (int i = 0; i < 8; i++)
        #pragma unroll
        for (int q = 0; q < 4; q++) acc[i][q] = 0ull;

    // staging thread mapping
    const int an = t >> 2;          // node 0..63
    const int ak = (t & 3) << 2;    // k sub 0,4,8,12
    const int bk = t >> 6;          // 0..3
    const int bo = (t & 63) << 2;   // col

    float4 apre, bpre[4];
    apre = *reinterpret_cast<const float4*>(s_g + (size_t)(node0 + an) * 256 + ak);
    #pragma unroll
    for (int r = 0; r < 4; r++)
        bpre[r] = *reinterpret_cast<const float4*>(g_Wt + (bk + r * 4) * 256 + bo);

    #define LOAD_AB(kk, areg, breg)                                         \
        do {                                                                \
            _Pragma("unroll")                                               \
            for (int i_ = 0; i_ < 8; i_++)                                  \
                areg[i_] = A2u[(kk) * 64 + (w << 3) + i_];                  \
            _Pragma("unroll")                                               \
            for (int q_ = 0; q_ < 4; q_++)                                  \
                breg[q_] = B2u[(kk) * 128 + l + (q_ << 5)];                 \
        } while (0)

    #define FMA_STEP(areg, breg)                                            \
        do {                                                                \
            _Pragma("unroll")                                               \
            for (int i_ = 0; i_ < 8; i_++)                                  \
                _Pragma("unroll")                                           \
                for (int q_ = 0; q_ < 4; q_++)                              \
                    fma2(acc[i_][q_], areg[i_], breg[q_]);                  \
        } while (0)

    for (int c = 0; c < 18; c++) {
        __syncthreads();
        A2u[(ak + 0) * 64 + an] = pack2(apre.x);
        A2u[(ak + 1) * 64 + an] = pack2(apre.y);
        A2u[(ak + 2) * 64 + an] = pack2(apre.z);
        A2u[(ak + 3) * 64 + an] = pack2(apre.w);
        #pragma unroll
        for (int r = 0; r < 4; r++)
            *reinterpret_cast<float4*>(B_s + (bk + r * 4) * 256 + bo) = bpre[r];
        __syncthreads();

        if (c < 17) {   // register-prefetch next chunk
            int k0 = (c + 1) * 16;
            if (k0 < 256)
                apre = *reinterpret_cast<const float4*>(s_g + (size_t)(node0 + an) * 256 + k0 + ak);
            else
                apre = *reinterpret_cast<const float4*>(sh + an * 32 + (k0 - 256) + ak);
            #pragma unroll
            for (int r = 0; r < 4; r++)
                bpre[r] = *reinterpret_cast<const float4*>(g_Wt + (size_t)(k0 + bk + r * 4) * 256 + bo);
        }

        // register double-buffered kk loop
        ull aA[8], bA[4], aB[8], bB[4];
        LOAD_AB(0, aA, bA);
        #pragma unroll
        for (int kk = 0; kk < 16; kk += 2) {
            LOAD_AB(kk + 1, aB, bB);
            FMA_STEP(aA, bA);
            if (kk + 2 < 16) LOAD_AB(kk + 2, aA, bA);
            FMA_STEP(aB, bB);
        }
    }

    // ---------------- stage 3: bias + relu out + sigmoid to smem ----------------
    ull biasp[4];
    #pragma unroll
    for (int q = 0; q < 4; q++)
        biasp[q] = *reinterpret_cast<const ull*>(Wmb + 2 * l + 64 * q);

    #pragma unroll
    for (int i = 0; i < 8; i++) {
        int ln = (w << 3) + i;
        size_t gn = (size_t)(node0 + ln);
        #pragma unroll
        for (int q = 0; q < 4; q++) {
            float2 v = unpack2(acc[i][q]);
            float2 b = unpack2(biasp[q]);
            float m0 = v.x + b.x;
            float m1 = v.y + b.y;
            *reinterpret_cast<ull*>(out + gn * 256 + 2 * l + 64 * q) =
                pack2(fmaxf(m0, 0.f), fmaxf(m1, 0.f));
            *reinterpret_cast<ull*>(S_s + ln * 256 + 2 * l + 64 * q) =
                pack2(sigmoidf_fast(m0), sigmoidf_fast(m1));
        }
    }
    __syncthreads();

    // ---------------- stage 4: gate GEMM + V_mu + V_dash ----------------
    const int m  = t & 31;
    const int nb = t >> 5;   // nodes nb, nb+8, ..., nb+56

    ull ag[8];
    #pragma unroll
    for (int j = 0; j < 8; j++) ag[j] = 0ull;

    const float* WgF = sm_ + OFF_WG;
    for (int kp2 = 0; kp2 < 64; kp2++) {
        F4U wv;
        wv.f = *reinterpret_cast<const float4*>(WgF + (kp2 * 32 + m) * 4);
        #pragma unroll
        for (int j = 0; j < 8; j++) {
            F4U sv;
            sv.f = *reinterpret_cast<const float4*>(S_s + (nb + j * 8) * 256 + 4 * kp2);
            fma2(ag[j], sv.u[0], wv.u[0]);
            fma2(ag[j], sv.u[1], wv.u[1]);
        }
    }
    float gb = Wgb[m];
    float gate[8];
    #pragma unroll
    for (int j = 0; j < 8; j++) {
        float2 v = unpack2(ag[j]);
        gate[j] = sigmoidf_fast(v.x + v.y + gb);
    }

    #pragma unroll
    for (int j = 0; j < 8; j++) {
        int n = nb + j * 8;
        float ax = 0.f, ay = 0.f, az = 0.f;
        const float* vr = Vh + n * 96;
        #pragma unroll
        for (int h = 0; h < 32; h++) {
            float wmu = WmuT[h * 32 + m];
            ax = fmaf(wmu, vr[h * 3 + 0], ax);
            ay = fmaf(wmu, vr[h * 3 + 1], ay);
            az = fmaf(wmu, vr[h * 3 + 2], az);
        }
        float g = gate[j];
        size_t base = (size_t)N * 256 + ((size_t)(node0 + n) * 32 + m) * 3;
        out[base + 0] = g * ax;
        out[base + 1] = g * ay;
        out[base + 2] = g * az;
    }
}

extern "C" void kernel_launch(void* const* d_in, const int* in_sizes, int n_in,
                              void* d_out, int out_size) {
    const float* s   = (const float*)d_in[0];
    const float* V   = (const float*)d_in[1];
    const float* Wh  = (const float*)d_in[2];
    const float* Wmu = (const float*)d_in[3];
    const float* Wm  = (const float*)d_in[4];
    const float* Wmb = (const float*)d_in[5];
    const float* Wg  = (const float*)d_in[6];
    const float* Wgb = (const float*)d_in[7];
    float* out = (float*)d_out;

    const int N = in_sizes[0] / 256;

    cudaFuncSetAttribute(gvp_kernel, cudaFuncAttributeMaxDynamicSharedMemorySize, SMEM_BYTES);

    prep_transpose<<<(288 * 256 + 255) / 256, 256>>>(Wm);
    gvp_kernel<<<N / NODES_PER_CTA, TPB, SMEM_BYTES>>>(s, V, Wh, Wmu, Wmb, Wg, Wgb, out, N);
}